// round 1
// baseline (speedup 1.0000x reference)
#include <cuda_runtime.h>
#include <math.h>
#include <stdint.h>

#define NN   100000
#define EE   1600000
#define GG   512
#define IN_C 96
#define HID  128
#define NCLS 100

// ---------------- scratch (device globals; no allocation) ----------------
__device__ float d_ew[EE];
__device__ int   d_pos[EE];
__device__ int   d_cnt[NN];
__device__ int   d_rowptr[NN + 1];
__device__ int   d_src[EE];
__device__ float d_nrm[EE];
__device__ float d_deg[NN];
__device__ float d_dis[NN];
__device__ float d_hw  [(size_t)NN * HID];
__device__ float d_curA[(size_t)NN * HID];
__device__ float d_curB[(size_t)NN * HID];
__device__ float d_res0[(size_t)NN * HID];
__device__ float d_xm  [(size_t)NN * HID];
__device__ int   d_gstart[GG + 1];
__device__ float d_gmean[GG * HID];
__device__ float d_gmaxv[GG * HID];

// ---------------- init ----------------
__global__ void init_k() {
    int i = blockIdx.x * blockDim.x + threadIdx.x;
    if (i < NN) { d_deg[i] = 1.0f; d_cnt[i] = 0; }   // deg starts at 1 (self loop w=1)
    if (i <= GG) d_gstart[i] = NN;
}

// ---------------- edge encoder: ew = softplus(MLP(edge_attr)) + 1e-4 ----------------
__global__ __launch_bounds__(256) void edge_mlp_k(
    const float* __restrict__ ea, const float* __restrict__ W1,
    const float* __restrict__ b1, const float* __restrict__ W2,
    const float* __restrict__ b2)
{
    __shared__ float W1s[8 * 128];
    __shared__ float b1s[128];
    __shared__ float W2s[128];
    int tid = threadIdx.x;
    for (int i = tid; i < 8 * 128; i += 256) W1s[i] = W1[i];
    if (tid < 128) { b1s[tid] = b1[tid]; W2s[tid] = W2[tid]; }
    __syncthreads();
    int e = blockIdx.x * 256 + tid;
    if (e >= EE) return;
    float4 a0 = *(const float4*)(ea + (size_t)e * 8);
    float4 a1 = *(const float4*)(ea + (size_t)e * 8 + 4);
    float a[8] = {a0.x, a0.y, a0.z, a0.w, a1.x, a1.y, a1.z, a1.w};
    const float4* W1v = (const float4*)W1s;
    const float4* b1v = (const float4*)b1s;
    const float4* W2v = (const float4*)W2s;
    float acc = 0.f;
    #pragma unroll 8
    for (int j4 = 0; j4 < 32; j4++) {
        float4 h = b1v[j4];
        #pragma unroll
        for (int k = 0; k < 8; k++) {
            float4 w = W1v[k * 32 + j4];
            h.x = fmaf(a[k], w.x, h.x);
            h.y = fmaf(a[k], w.y, h.y);
            h.z = fmaf(a[k], w.z, h.z);
            h.w = fmaf(a[k], w.w, h.w);
        }
        h.x = fmaxf(h.x, 0.f); h.y = fmaxf(h.y, 0.f);
        h.z = fmaxf(h.z, 0.f); h.w = fmaxf(h.w, 0.f);
        float4 w2 = W2v[j4];
        acc = fmaf(h.x, w2.x, acc);
        acc = fmaf(h.y, w2.y, acc);
        acc = fmaf(h.z, w2.z, acc);
        acc = fmaf(h.w, w2.w, acc);
    }
    float x = acc + b2[0];
    float sp = (x > 15.f) ? x : log1pf(expf(x));
    d_ew[e] = sp + 1e-4f;
}

// ---------------- degree accumulation + per-dest counting ----------------
__global__ void count_deg_k(const int* __restrict__ col) {
    int e = blockIdx.x * blockDim.x + threadIdx.x;
    if (e >= EE) return;
    int c = col[e];
    d_pos[e] = atomicAdd(&d_cnt[c], 1);
    atomicAdd(&d_deg[c], d_ew[e]);
}

__global__ void dis_k() {
    int i = blockIdx.x * blockDim.x + threadIdx.x;
    if (i < NN) d_dis[i] = rsqrtf(d_deg[i]);   // deg >= 1 always
}

// ---------------- single-block exclusive scan -> rowptr ----------------
__global__ __launch_bounds__(1024) void scan_k() {
    __shared__ int wsum[32];
    int tid = threadIdx.x, lane = tid & 31, wid = tid >> 5;
    int carry = 0;
    if (tid == 0) d_rowptr[0] = 0;
    for (int base = 0; base < NN; base += 1024) {
        int i = base + tid;
        int v = (i < NN) ? d_cnt[i] : 0;
        int s = v;
        #pragma unroll
        for (int o = 1; o < 32; o <<= 1) {
            int t = __shfl_up_sync(0xffffffffu, s, o);
            if (lane >= o) s += t;
        }
        if (lane == 31) wsum[wid] = s;
        __syncthreads();
        if (wid == 0) {
            int ws = wsum[lane];
            #pragma unroll
            for (int o = 1; o < 32; o <<= 1) {
                int t = __shfl_up_sync(0xffffffffu, ws, o);
                if (lane >= o) ws += t;
            }
            wsum[lane] = ws;
        }
        __syncthreads();
        int wexcl = (wid > 0) ? wsum[wid - 1] : 0;
        if (i < NN) d_rowptr[i + 1] = carry + wexcl + s;
        carry += wsum[31];
        __syncthreads();
    }
}

// ---------------- fill CSR: sorted-by-dest (src, norm) ----------------
__global__ void fill_k(const int* __restrict__ row, const int* __restrict__ col) {
    int e = blockIdx.x * blockDim.x + threadIdx.x;
    if (e >= EE) return;
    int r = row[e], c = col[e];
    int j = d_rowptr[c] + d_pos[e];
    d_src[j] = r;
    d_nrm[j] = d_dis[r] * d_ew[e] * d_dis[c];
}

// ---------------- GEMM: C[M,128] = A[M,K] @ B[K,128] (+bias) ----------------
// asel: 0 -> Ain param, 1 -> d_curA, 2 -> d_curB ; osel: 0 -> d_hw, 1 -> d_res0
__global__ __launch_bounds__(256) void gemm_k(
    const float* __restrict__ Ain, const float* __restrict__ B,
    const float* __restrict__ bias, int asel, int osel, int M, int K)
{
    const float* A = (asel == 1) ? d_curA : (asel == 2) ? d_curB : Ain;
    float* C = (osel == 1) ? d_res0 : d_hw;
    __shared__ float As[32][64];
    __shared__ float Bs[32][128];
    int tid = threadIdx.x;
    int r0 = blockIdx.x * 64;
    int ty = tid >> 4, tx = tid & 15;
    float acc[4][8];
    #pragma unroll
    for (int r = 0; r < 4; r++)
        #pragma unroll
        for (int c = 0; c < 8; c++) acc[r][c] = 0.f;

    for (int kb = 0; kb < K; kb += 32) {
        #pragma unroll
        for (int h = 0; h < 2; h++) {
            int f = tid + h * 256;
            int row = f >> 3;
            int kq = (f & 7) << 2;
            float4 a4 = make_float4(0.f, 0.f, 0.f, 0.f);
            if (r0 + row < M)
                a4 = *(const float4*)(A + (size_t)(r0 + row) * K + kb + kq);
            As[kq][row] = a4.x; As[kq + 1][row] = a4.y;
            As[kq + 2][row] = a4.z; As[kq + 3][row] = a4.w;
        }
        #pragma unroll
        for (int h = 0; h < 4; h++) {
            int f = tid + h * 256;
            int kk = f >> 5;
            int c = (f & 31) << 2;
            *(float4*)&Bs[kk][c] = *(const float4*)(B + (size_t)(kb + kk) * HID + c);
        }
        __syncthreads();
        #pragma unroll
        for (int kk = 0; kk < 32; kk++) {
            float4 a4 = *(const float4*)&As[kk][ty << 2];
            float4 b0 = *(const float4*)&Bs[kk][tx << 3];
            float4 b1 = *(const float4*)&Bs[kk][(tx << 3) + 4];
            float av[4] = {a4.x, a4.y, a4.z, a4.w};
            float bv[8] = {b0.x, b0.y, b0.z, b0.w, b1.x, b1.y, b1.z, b1.w};
            #pragma unroll
            for (int r = 0; r < 4; r++)
                #pragma unroll
                for (int c = 0; c < 8; c++)
                    acc[r][c] = fmaf(av[r], bv[c], acc[r][c]);
        }
        __syncthreads();
    }
    #pragma unroll
    for (int r = 0; r < 4; r++) {
        int row = r0 + (ty << 2) + r;
        if (row < M) {
            float o[8];
            #pragma unroll
            for (int c = 0; c < 8; c++) o[c] = acc[r][c];
            if (bias) {
                #pragma unroll
                for (int c = 0; c < 8; c++) o[c] += bias[(tx << 3) + c];
            }
            *(float4*)(C + (size_t)row * HID + (tx << 3)) = make_float4(o[0], o[1], o[2], o[3]);
            *(float4*)(C + (size_t)row * HID + (tx << 3) + 4) = make_float4(o[4], o[5], o[6], o[7]);
        }
    }
}

// ---------------- fused aggregate + bias + LN + residual + relu + mean-acc ----------------
// rsel: 0 -> d_res0, 1 -> d_curA, 2 -> d_curB ; osel: 1 -> d_curA, 2 -> d_curB
__global__ __launch_bounds__(256) void agg_ln_k(
    const float* __restrict__ cb, const float* __restrict__ gam,
    const float* __restrict__ bet, int rsel, int osel, int first)
{
    int n = (blockIdx.x * 256 + threadIdx.x) >> 5;
    if (n >= NN) return;
    int lane = threadIdx.x & 31;
    const float4* hw4 = (const float4*)d_hw;
    const float* resid = (rsel == 0) ? d_res0 : (rsel == 1) ? d_curA : d_curB;
    float* outp = (osel == 1) ? d_curA : d_curB;

    float dn = d_dis[n];
    float sn = dn * dn;
    float4 acc = ((const float4*)cb)[lane];
    float4 hv = hw4[(size_t)n * 32 + lane];
    acc.x = fmaf(sn, hv.x, acc.x);
    acc.y = fmaf(sn, hv.y, acc.y);
    acc.z = fmaf(sn, hv.z, acc.z);
    acc.w = fmaf(sn, hv.w, acc.w);

    int jb = d_rowptr[n], je = d_rowptr[n + 1];
    for (int j = jb; j < je; j++) {
        int s = d_src[j];
        float w = d_nrm[j];
        float4 m = hw4[(size_t)s * 32 + lane];
        acc.x = fmaf(w, m.x, acc.x);
        acc.y = fmaf(w, m.y, acc.y);
        acc.z = fmaf(w, m.z, acc.z);
        acc.w = fmaf(w, m.w, acc.w);
    }

    float ss = acc.x + acc.y + acc.z + acc.w;
    #pragma unroll
    for (int o = 16; o > 0; o >>= 1) ss += __shfl_xor_sync(0xffffffffu, ss, o);
    float mu = ss * (1.f / 128.f);
    float dx0 = acc.x - mu, dx1 = acc.y - mu, dx2 = acc.z - mu, dx3 = acc.w - mu;
    float q = dx0 * dx0 + dx1 * dx1 + dx2 * dx2 + dx3 * dx3;
    #pragma unroll
    for (int o = 16; o > 0; o >>= 1) q += __shfl_xor_sync(0xffffffffu, q, o);
    float rstd = rsqrtf(q * (1.f / 128.f) + 1e-5f);

    float4 gv = ((const float4*)gam)[lane];
    float4 bv = ((const float4*)bet)[lane];
    float4 rv = ((const float4*)resid)[(size_t)n * 32 + lane];
    float4 h;
    h.x = fmaxf(fmaf(gv.x, dx0 * rstd, bv.x) + rv.x, 0.f);
    h.y = fmaxf(fmaf(gv.y, dx1 * rstd, bv.y) + rv.y, 0.f);
    h.z = fmaxf(fmaf(gv.z, dx2 * rstd, bv.z) + rv.z, 0.f);
    h.w = fmaxf(fmaf(gv.w, dx3 * rstd, bv.w) + rv.w, 0.f);

    ((float4*)outp)[(size_t)n * 32 + lane] = h;
    float4* xm4 = (float4*)d_xm;
    if (first) {
        xm4[(size_t)n * 32 + lane] = h;
    } else {
        float4 t = xm4[(size_t)n * 32 + lane];
        t.x += h.x; t.y += h.y; t.z += h.z; t.w += h.w;
        xm4[(size_t)n * 32 + lane] = t;
    }
}

// ---------------- graph segment boundaries (batch is sorted) ----------------
__global__ void mark_k(const int* __restrict__ batch) {
    int n = blockIdx.x * blockDim.x + threadIdx.x;
    if (n >= NN) return;
    int b = batch[n];
    if (n == 0 || batch[n - 1] != b) atomicMin(&d_gstart[b], n);
}

__global__ __launch_bounds__(512) void fix_k() {
    __shared__ int s[520];
    int t = threadIdx.x;
    s[t] = d_gstart[t];
    if (t == 0) s[GG] = NN;
    __syncthreads();
    for (int o = 1; o <= GG; o <<= 1) {
        int v = s[t];
        int u = (t + o <= GG) ? s[t + o] : NN;
        __syncthreads();
        s[t] = min(v, u);
        __syncthreads();
    }
    d_gstart[t] = s[t];
}

// ---------------- pooling: block per graph (mean + max of xm = acc/4) ----------------
__global__ __launch_bounds__(128) void pool_k() {
    int g = blockIdx.x, c = threadIdx.x;
    int s = d_gstart[g], e = d_gstart[g + 1];
    float sum = 0.f, mx = 0.f;
    for (int n = s; n < e; n++) {
        float v = d_xm[(size_t)n * HID + c] * 0.25f;
        sum += v;
        mx = fmaxf(mx, v);
    }
    int cnt = e - s;
    d_gmean[g * HID + c] = sum / (float)max(cnt, 1);
    d_gmaxv[g * HID + c] = mx;
}

// ---------------- head: relu(gfeat@hW1+hb1)@hW2+hb2 ----------------
__global__ __launch_bounds__(128) void head_k(
    const float* __restrict__ hW1, const float* __restrict__ hb1,
    const float* __restrict__ hW2, const float* __restrict__ hb2,
    float* __restrict__ out)
{
    __shared__ float gf[256];
    __shared__ float h1s[128];
    int g = blockIdx.x, t = threadIdx.x;
    gf[t] = d_gmean[g * HID + t];
    gf[128 + t] = d_gmaxv[g * HID + t];
    __syncthreads();
    float acc = hb1[t];
    #pragma unroll 8
    for (int k = 0; k < 256; k++) acc = fmaf(gf[k], hW1[k * HID + t], acc);
    h1s[t] = fmaxf(acc, 0.f);
    __syncthreads();
    if (t < NCLS) {
        float o = hb2[t];
        #pragma unroll 8
        for (int k = 0; k < 128; k++) o = fmaf(h1s[k], hW2[k * NCLS + t], o);
        out[g * NCLS + t] = o;
    }
}

// ---------------- launcher ----------------
extern "C" void kernel_launch(void* const* d_in, const int* in_sizes, int n_in,
                              void* d_out, int out_size) {
    const float* x     = (const float*)d_in[0];
    const int*   ei    = (const int*)d_in[1];   // [2,E]: row = ei, col = ei+E
    const int*   batch = (const int*)d_in[2];
    const float* ea    = (const float*)d_in[3];
    const float* eeW1  = (const float*)d_in[4];
    const float* eeb1  = (const float*)d_in[5];
    const float* eeW2  = (const float*)d_in[6];
    const float* eeb2  = (const float*)d_in[7];
    const float* W[4]  = {(const float*)d_in[8],  (const float*)d_in[10],
                          (const float*)d_in[12], (const float*)d_in[14]};
    const float* cb[4] = {(const float*)d_in[9],  (const float*)d_in[11],
                          (const float*)d_in[13], (const float*)d_in[15]};
    const float* gm[4] = {(const float*)d_in[16], (const float*)d_in[18],
                          (const float*)d_in[20], (const float*)d_in[22]};
    const float* be[4] = {(const float*)d_in[17], (const float*)d_in[19],
                          (const float*)d_in[21], (const float*)d_in[23]};
    const float* resW  = (const float*)d_in[24];
    const float* resB  = (const float*)d_in[25];
    const float* hW1   = (const float*)d_in[26];
    const float* hb1   = (const float*)d_in[27];
    const float* hW2   = (const float*)d_in[28];
    const float* hb2   = (const float*)d_in[29];
    float* out = (float*)d_out;

    const int nblkN = (NN + 255) / 256;
    const int nblkE = (EE + 255) / 256;
    const int gemmG = (NN + 63) / 64;
    const int aggG  = (NN + 7) / 8;

    init_k<<<nblkN, 256>>>();
    edge_mlp_k<<<nblkE, 256>>>(ea, eeW1, eeb1, eeW2, eeb2);
    count_deg_k<<<nblkE, 256>>>(ei + EE);
    dis_k<<<nblkN, 256>>>();
    scan_k<<<1, 1024>>>();
    fill_k<<<nblkE, 256>>>(ei, ei + EE);

    // residual projection for layer 0
    gemm_k<<<gemmG, 256>>>(x, resW, resB, /*asel=*/0, /*osel=*/1, NN, IN_C);

    // layer 0: x -> curA
    gemm_k<<<gemmG, 256>>>(x, W[0], nullptr, 0, 0, NN, IN_C);
    agg_ln_k<<<aggG, 256>>>(cb[0], gm[0], be[0], /*rsel=*/0, /*osel=*/1, 1);
    // layer 1: curA -> curB
    gemm_k<<<gemmG, 256>>>(nullptr, W[1], nullptr, 1, 0, NN, HID);
    agg_ln_k<<<aggG, 256>>>(cb[1], gm[1], be[1], 1, 2, 0);
    // layer 2: curB -> curA
    gemm_k<<<gemmG, 256>>>(nullptr, W[2], nullptr, 2, 0, NN, HID);
    agg_ln_k<<<aggG, 256>>>(cb[2], gm[2], be[2], 2, 1, 0);
    // layer 3: curA -> curB
    gemm_k<<<gemmG, 256>>>(nullptr, W[3], nullptr, 1, 0, NN, HID);
    agg_ln_k<<<aggG, 256>>>(cb[3], gm[3], be[3], 1, 2, 0);

    mark_k<<<nblkN, 256>>>(batch);
    fix_k<<<1, 512>>>();
    pool_k<<<GG, 128>>>();
    head_k<<<GG, 128>>>(hW1, hb1, hW2, hb2, out);
}

// round 3
// speedup vs baseline: 1.2926x; 1.2926x over previous
#include <cuda_runtime.h>
#include <cuda_bf16.h>
#include <math.h>
#include <stdint.h>

#define NN   100000
#define EE   1600000
#define GG   512
#define IN_C 96
#define HID  128
#define NCLS 100

// ---------------- scratch (device globals; no allocation) ----------------
__device__ float d_ew[EE];
__device__ int   d_pos[EE];
__device__ int   d_cnt[NN];
__device__ int   d_rowptr[NN + 1];
__device__ int   d_src[EE];
__device__ float d_nrm[EE];
__device__ float d_deg[NN];
__device__ float d_dis[NN];
__device__ float d_hw  [(size_t)NN * HID];
__device__ float d_curA[(size_t)NN * HID];
__device__ float d_curB[(size_t)NN * HID];
__device__ float d_res0[(size_t)NN * HID];
__device__ float d_xm  [(size_t)NN * HID];
__device__ int   d_gstart[GG + 1];
__device__ float d_gmean[GG * HID];
__device__ float d_gmaxv[GG * HID];
// pre-split weights, n-major [128 n][128 k] bf16, hi and lo parts, 5 matrices
__device__ __nv_bfloat16 d_Bh[5 * 128 * 128];
__device__ __nv_bfloat16 d_Bl[5 * 128 * 128];

// ---------------- init ----------------
__global__ void init_k() {
    int i = blockIdx.x * blockDim.x + threadIdx.x;
    if (i < NN) { d_deg[i] = 1.0f; d_cnt[i] = 0; }
    if (i <= GG) d_gstart[i] = NN;
}

// ---------------- edge encoder ----------------
__global__ __launch_bounds__(256) void edge_mlp_k(
    const float* __restrict__ ea, const float* __restrict__ W1,
    const float* __restrict__ b1, const float* __restrict__ W2,
    const float* __restrict__ b2)
{
    __shared__ float W1s[8 * 128];
    __shared__ float b1s[128];
    __shared__ float W2s[128];
    int tid = threadIdx.x;
    for (int i = tid; i < 8 * 128; i += 256) W1s[i] = W1[i];
    if (tid < 128) { b1s[tid] = b1[tid]; W2s[tid] = W2[tid]; }
    __syncthreads();
    int e = blockIdx.x * 256 + tid;
    if (e >= EE) return;
    float4 a0 = *(const float4*)(ea + (size_t)e * 8);
    float4 a1 = *(const float4*)(ea + (size_t)e * 8 + 4);
    float a[8] = {a0.x, a0.y, a0.z, a0.w, a1.x, a1.y, a1.z, a1.w};
    const float4* W1v = (const float4*)W1s;
    const float4* b1v = (const float4*)b1s;
    const float4* W2v = (const float4*)W2s;
    float acc = 0.f;
    #pragma unroll 8
    for (int j4 = 0; j4 < 32; j4++) {
        float4 h = b1v[j4];
        #pragma unroll
        for (int k = 0; k < 8; k++) {
            float4 w = W1v[k * 32 + j4];
            h.x = fmaf(a[k], w.x, h.x);
            h.y = fmaf(a[k], w.y, h.y);
            h.z = fmaf(a[k], w.z, h.z);
            h.w = fmaf(a[k], w.w, h.w);
        }
        h.x = fmaxf(h.x, 0.f); h.y = fmaxf(h.y, 0.f);
        h.z = fmaxf(h.z, 0.f); h.w = fmaxf(h.w, 0.f);
        float4 w2 = W2v[j4];
        acc = fmaf(h.x, w2.x, acc);
        acc = fmaf(h.y, w2.y, acc);
        acc = fmaf(h.z, w2.z, acc);
        acc = fmaf(h.w, w2.w, acc);
    }
    float x = acc + b2[0];
    float sp = (x > 15.f) ? x : log1pf(expf(x));
    d_ew[e] = sp + 1e-4f;
}

// ---------------- degree + counting ----------------
__global__ void count_deg_k(const int* __restrict__ col) {
    int e = blockIdx.x * blockDim.x + threadIdx.x;
    if (e >= EE) return;
    int c = col[e];
    d_pos[e] = atomicAdd(&d_cnt[c], 1);
    atomicAdd(&d_deg[c], d_ew[e]);
}

__global__ void dis_k() {
    int i = blockIdx.x * blockDim.x + threadIdx.x;
    if (i < NN) d_dis[i] = rsqrtf(d_deg[i]);
}

// ---------------- single-block exclusive scan -> rowptr ----------------
__global__ __launch_bounds__(1024) void scan_k() {
    __shared__ int wsum[32];
    int tid = threadIdx.x, lane = tid & 31, wid = tid >> 5;
    int carry = 0;
    if (tid == 0) d_rowptr[0] = 0;
    for (int base = 0; base < NN; base += 1024) {
        int i = base + tid;
        int v = (i < NN) ? d_cnt[i] : 0;
        int s = v;
        #pragma unroll
        for (int o = 1; o < 32; o <<= 1) {
            int t = __shfl_up_sync(0xffffffffu, s, o);
            if (lane >= o) s += t;
        }
        if (lane == 31) wsum[wid] = s;
        __syncthreads();
        if (wid == 0) {
            int ws = wsum[lane];
            #pragma unroll
            for (int o = 1; o < 32; o <<= 1) {
                int t = __shfl_up_sync(0xffffffffu, ws, o);
                if (lane >= o) ws += t;
            }
            wsum[lane] = ws;
        }
        __syncthreads();
        int wexcl = (wid > 0) ? wsum[wid - 1] : 0;
        if (i < NN) d_rowptr[i + 1] = carry + wexcl + s;
        carry += wsum[31];
        __syncthreads();
    }
}

// ---------------- fill CSR ----------------
__global__ void fill_k(const int* __restrict__ row, const int* __restrict__ col) {
    int e = blockIdx.x * blockDim.x + threadIdx.x;
    if (e >= EE) return;
    int r = row[e], c = col[e];
    int j = d_rowptr[c] + d_pos[e];
    d_src[j] = r;
    d_nrm[j] = d_dis[r] * d_ew[e] * d_dis[c];
}

// ---------------- weight prep: split fp32 -> bf16 hi/lo, n-major [n][k] ----------------
// matrices: 0=resW(K=96) 1=W0(K=96) 2=W1 3=W2 4=W3 (K=128)
__global__ __launch_bounds__(128) void prep_k(
    const float* __restrict__ resW, const float* __restrict__ W0,
    const float* __restrict__ W1, const float* __restrict__ W2,
    const float* __restrict__ W3)
{
    int m = blockIdx.x, n = threadIdx.x;
    const float* W; int K;
    switch (m) {
        case 0: W = resW; K = 96; break;
        case 1: W = W0;   K = 96; break;
        case 2: W = W1;   K = 128; break;
        case 3: W = W2;   K = 128; break;
        default: W = W3;  K = 128; break;
    }
    __nv_bfloat16* bh = d_Bh + (size_t)m * 16384 + (size_t)n * 128;
    __nv_bfloat16* bl = d_Bl + (size_t)m * 16384 + (size_t)n * 128;
    for (int k = 0; k < 128; k++) {
        float v = (k < K) ? W[(size_t)k * HID + n] : 0.f;
        __nv_bfloat16 h = __float2bfloat16_rn(v);
        bh[k] = h;
        bl[k] = __float2bfloat16_rn(v - __bfloat162float(h));
    }
}

// ---------------- HMMA bf16 split GEMM: C[M,128] = A[M,K] @ W + (bias) ----------------
// smem buffers: Ahi/Alo m-major [128 m][PITCH], Bh/Bl n-major [128 n][PITCH]
#define PITCH 136
#define BUFSZ (128 * PITCH)
#define SMEM_GEMM (4 * BUFSZ * 2)

__device__ __forceinline__ void mma16816(float* c, const uint32_t* a, const uint32_t* b) {
    asm volatile(
        "mma.sync.aligned.m16n8k16.row.col.f32.bf16.bf16.f32 "
        "{%0,%1,%2,%3}, {%4,%5,%6,%7}, {%8,%9}, {%0,%1,%2,%3};"
        : "+f"(c[0]), "+f"(c[1]), "+f"(c[2]), "+f"(c[3])
        : "r"(a[0]), "r"(a[1]), "r"(a[2]), "r"(a[3]), "r"(b[0]), "r"(b[1]));
}

// asel: 0 -> Ain, 1 -> d_curA, 2 -> d_curB ; osel: 0 -> d_hw, 1 -> d_res0
__global__ __launch_bounds__(256) void mma_gemm_k(
    const float* __restrict__ Ain, int asel, int osel, int mat,
    int lda, const float* __restrict__ bias)
{
    extern __shared__ __nv_bfloat16 sm[];
    __nv_bfloat16* AhiS = sm;
    __nv_bfloat16* AloS = sm + BUFSZ;
    __nv_bfloat16* BhS  = sm + 2 * BUFSZ;
    __nv_bfloat16* BlS  = sm + 3 * BUFSZ;
    __shared__ float biasS[128];

    const float* A = (asel == 1) ? d_curA : (asel == 2) ? d_curB : Ain;
    float* C = (osel == 1) ? d_res0 : d_hw;
    int tid = threadIdx.x;
    int r0 = blockIdx.x * 128;

    if (tid < 128) biasS[tid] = bias ? bias[tid] : 0.f;

    // stage A (fp32 -> hi/lo bf16)
    {
        int rr = tid >> 5;           // 0..7
        int cc = (tid & 31) * 4;     // 0..124
        #pragma unroll 4
        for (int it = 0; it < 16; it++) {
            int r = it * 8 + rr;
            int R = r0 + r;
            float4 v = make_float4(0.f, 0.f, 0.f, 0.f);
            if (R < NN && cc < lda)
                v = *(const float4*)(A + (size_t)R * lda + cc);
            __nv_bfloat16 h0 = __float2bfloat16_rn(v.x);
            __nv_bfloat16 h1 = __float2bfloat16_rn(v.y);
            __nv_bfloat16 h2 = __float2bfloat16_rn(v.z);
            __nv_bfloat16 h3 = __float2bfloat16_rn(v.w);
            __nv_bfloat16 l0 = __float2bfloat16_rn(v.x - __bfloat162float(h0));
            __nv_bfloat16 l1 = __float2bfloat16_rn(v.y - __bfloat162float(h1));
            __nv_bfloat16 l2 = __float2bfloat16_rn(v.z - __bfloat162float(h2));
            __nv_bfloat16 l3 = __float2bfloat16_rn(v.w - __bfloat162float(h3));
            uint2 ph, pl;
            ph.x = ((uint32_t)__bfloat16_as_ushort(h1) << 16) | __bfloat16_as_ushort(h0);
            ph.y = ((uint32_t)__bfloat16_as_ushort(h3) << 16) | __bfloat16_as_ushort(h2);
            pl.x = ((uint32_t)__bfloat16_as_ushort(l1) << 16) | __bfloat16_as_ushort(l0);
            pl.y = ((uint32_t)__bfloat16_as_ushort(l3) << 16) | __bfloat16_as_ushort(l2);
            *(uint2*)(AhiS + r * PITCH + cc) = ph;
            *(uint2*)(AloS + r * PITCH + cc) = pl;
        }
    }
    // stage B (already split, n-major)
    {
        int rr = tid >> 5;
        int cc = (tid & 31) * 4;
        const __nv_bfloat16* gh = d_Bh + (size_t)mat * 16384;
        const __nv_bfloat16* gl = d_Bl + (size_t)mat * 16384;
        #pragma unroll 4
        for (int it = 0; it < 16; it++) {
            int n = it * 8 + rr;
            *(uint2*)(BhS + n * PITCH + cc) = *(const uint2*)(gh + n * 128 + cc);
            *(uint2*)(BlS + n * PITCH + cc) = *(const uint2*)(gl + n * 128 + cc);
        }
    }
    __syncthreads();

    int wid = tid >> 5, lane = tid & 31;
    int g = lane >> 2, tig = lane & 3;
    int wr = (wid & 3) * 32;          // warp M base (4 warps over 128)
    int wc = (wid >> 2) * 64;         // warp N base (2 warps over 128)

    float cacc[2][8][4];
    #pragma unroll
    for (int mt = 0; mt < 2; mt++)
        #pragma unroll
        for (int nt = 0; nt < 8; nt++)
            #pragma unroll
            for (int q = 0; q < 4; q++) cacc[mt][nt][q] = 0.f;

    #pragma unroll
    for (int p = 0; p < 3; p++) {
        const __nv_bfloat16* As = (p == 1) ? AloS : AhiS;
        const __nv_bfloat16* Bs = (p == 2) ? BlS : BhS;
        #pragma unroll
        for (int ks = 0; ks < 8; ks++) {
            int k0 = ks * 16;
            uint32_t af[2][4];
            #pragma unroll
            for (int mt = 0; mt < 2; mt++) {
                const __nv_bfloat16* base = As + (wr + mt * 16) * PITCH + k0;
                af[mt][0] = *(const uint32_t*)(base + g * PITCH + 2 * tig);
                af[mt][1] = *(const uint32_t*)(base + (g + 8) * PITCH + 2 * tig);
                af[mt][2] = *(const uint32_t*)(base + g * PITCH + 8 + 2 * tig);
                af[mt][3] = *(const uint32_t*)(base + (g + 8) * PITCH + 8 + 2 * tig);
            }
            #pragma unroll
            for (int nt = 0; nt < 8; nt++) {
                uint32_t bf[2];
                const __nv_bfloat16* nb = Bs + (wc + nt * 8 + g) * PITCH + k0;
                bf[0] = *(const uint32_t*)(nb + 2 * tig);
                bf[1] = *(const uint32_t*)(nb + 8 + 2 * tig);
                mma16816(cacc[0][nt], af[0], bf);
                mma16816(cacc[1][nt], af[1], bf);
            }
        }
    }

    // epilogue
    #pragma unroll
    for (int mt = 0; mt < 2; mt++) {
        int row = r0 + wr + mt * 16 + g;
        #pragma unroll
        for (int nt = 0; nt < 8; nt++) {
            int col = wc + nt * 8 + 2 * tig;
            float b0 = biasS[col], b1 = biasS[col + 1];
            if (row < NN) {
                float2 o = make_float2(cacc[mt][nt][0] + b0, cacc[mt][nt][1] + b1);
                *(float2*)(C + (size_t)row * HID + col) = o;
            }
            if (row + 8 < NN) {
                float2 o = make_float2(cacc[mt][nt][2] + b0, cacc[mt][nt][3] + b1);
                *(float2*)(C + (size_t)(row + 8) * HID + col) = o;
            }
        }
    }
}

// ---------------- fused aggregate + bias + LN + residual + relu + mean-acc ----------------
__global__ __launch_bounds__(256) void agg_ln_k(
    const float* __restrict__ cb, const float* __restrict__ gam,
    const float* __restrict__ bet, int rsel, int osel, int first)
{
    int n = (blockIdx.x * 256 + threadIdx.x) >> 5;
    if (n >= NN) return;
    int lane = threadIdx.x & 31;
    const float4* hw4 = (const float4*)d_hw;
    const float* resid = (rsel == 0) ? d_res0 : (rsel == 1) ? d_curA : d_curB;
    float* outp = (osel == 1) ? d_curA : d_curB;

    float dn = d_dis[n];
    float sn = dn * dn;
    float4 acc = ((const float4*)cb)[lane];
    float4 hv = hw4[(size_t)n * 32 + lane];
    acc.x = fmaf(sn, hv.x, acc.x);
    acc.y = fmaf(sn, hv.y, acc.y);
    acc.z = fmaf(sn, hv.z, acc.z);
    acc.w = fmaf(sn, hv.w, acc.w);

    int jb = d_rowptr[n], je = d_rowptr[n + 1];
    for (int j = jb; j < je; j++) {
        int s = d_src[j];
        float w = d_nrm[j];
        float4 m = hw4[(size_t)s * 32 + lane];
        acc.x = fmaf(w, m.x, acc.x);
        acc.y = fmaf(w, m.y, acc.y);
        acc.z = fmaf(w, m.z, acc.z);
        acc.w = fmaf(w, m.w, acc.w);
    }

    float ss = acc.x + acc.y + acc.z + acc.w;
    #pragma unroll
    for (int o = 16; o > 0; o >>= 1) ss += __shfl_xor_sync(0xffffffffu, ss, o);
    float mu = ss * (1.f / 128.f);
    float dx0 = acc.x - mu, dx1 = acc.y - mu, dx2 = acc.z - mu, dx3 = acc.w - mu;
    float q = dx0 * dx0 + dx1 * dx1 + dx2 * dx2 + dx3 * dx3;
    #pragma unroll
    for (int o = 16; o > 0; o >>= 1) q += __shfl_xor_sync(0xffffffffu, q, o);
    float rstd = rsqrtf(q * (1.f / 128.f) + 1e-5f);

    float4 gv = ((const float4*)gam)[lane];
    float4 bv = ((const float4*)bet)[lane];
    float4 rv = ((const float4*)resid)[(size_t)n * 32 + lane];
    float4 h;
    h.x = fmaxf(fmaf(gv.x, dx0 * rstd, bv.x) + rv.x, 0.f);
    h.y = fmaxf(fmaf(gv.y, dx1 * rstd, bv.y) + rv.y, 0.f);
    h.z = fmaxf(fmaf(gv.z, dx2 * rstd, bv.z) + rv.z, 0.f);
    h.w = fmaxf(fmaf(gv.w, dx3 * rstd, bv.w) + rv.w, 0.f);

    ((float4*)outp)[(size_t)n * 32 + lane] = h;
    float4* xm4 = (float4*)d_xm;
    if (first) {
        xm4[(size_t)n * 32 + lane] = h;
    } else {
        float4 t = xm4[(size_t)n * 32 + lane];
        t.x += h.x; t.y += h.y; t.z += h.z; t.w += h.w;
        xm4[(size_t)n * 32 + lane] = t;
    }
}

// ---------------- graph segment boundaries ----------------
__global__ void mark_k(const int* __restrict__ batch) {
    int n = blockIdx.x * blockDim.x + threadIdx.x;
    if (n >= NN) return;
    int b = batch[n];
    if (n == 0 || batch[n - 1] != b) atomicMin(&d_gstart[b], n);
}

__global__ __launch_bounds__(512) void fix_k() {
    __shared__ int s[520];
    int t = threadIdx.x;
    s[t] = d_gstart[t];
    if (t == 0) s[GG] = NN;
    __syncthreads();
    for (int o = 1; o <= GG; o <<= 1) {
        int v = s[t];
        int u = (t + o <= GG) ? s[t + o] : NN;
        __syncthreads();
        s[t] = min(v, u);
        __syncthreads();
    }
    d_gstart[t] = s[t];
}

// ---------------- pooling ----------------
__global__ __launch_bounds__(128) void pool_k() {
    int g = blockIdx.x, c = threadIdx.x;
    int s = d_gstart[g], e = d_gstart[g + 1];
    float sum = 0.f, mx = 0.f;
    for (int n = s; n < e; n++) {
        float v = d_xm[(size_t)n * HID + c] * 0.25f;
        sum += v;
        mx = fmaxf(mx, v);
    }
    int cnt = e - s;
    d_gmean[g * HID + c] = sum / (float)max(cnt, 1);
    d_gmaxv[g * HID + c] = mx;
}

// ---------------- head ----------------
__global__ __launch_bounds__(128) void head_k(
    const float* __restrict__ hW1, const float* __restrict__ hb1,
    const float* __restrict__ hW2, const float* __restrict__ hb2,
    float* __restrict__ out)
{
    __shared__ float gf[256];
    __shared__ float h1s[128];
    int g = blockIdx.x, t = threadIdx.x;
    gf[t] = d_gmean[g * HID + t];
    gf[128 + t] = d_gmaxv[g * HID + t];
    __syncthreads();
    float acc = hb1[t];
    #pragma unroll 8
    for (int k = 0; k < 256; k++) acc = fmaf(gf[k], hW1[k * HID + t], acc);
    h1s[t] = fmaxf(acc, 0.f);
    __syncthreads();
    if (t < NCLS) {
        float o = hb2[t];
        #pragma unroll 8
        for (int k = 0; k < 128; k++) o = fmaf(h1s[k], hW2[k * NCLS + t], o);
        out[g * NCLS + t] = o;
    }
}

// ---------------- launcher ----------------
extern "C" void kernel_launch(void* const* d_in, const int* in_sizes, int n_in,
                              void* d_out, int out_size) {
    const float* x     = (const float*)d_in[0];
    const int*   ei    = (const int*)d_in[1];
    const int*   batch = (const int*)d_in[2];
    const float* ea    = (const float*)d_in[3];
    const float* eeW1  = (const float*)d_in[4];
    const float* eeb1  = (const float*)d_in[5];
    const float* eeW2  = (const float*)d_in[6];
    const float* eeb2  = (const float*)d_in[7];
    const float* W[4]  = {(const float*)d_in[8],  (const float*)d_in[10],
                          (const float*)d_in[12], (const float*)d_in[14]};
    const float* cbp[4]= {(const float*)d_in[9],  (const float*)d_in[11],
                          (const float*)d_in[13], (const float*)d_in[15]};
    const float* gm[4] = {(const float*)d_in[16], (const float*)d_in[18],
                          (const float*)d_in[20], (const float*)d_in[22]};
    const float* be[4] = {(const float*)d_in[17], (const float*)d_in[19],
                          (const float*)d_in[21], (const float*)d_in[23]};
    const float* resW  = (const float*)d_in[24];
    const float* resB  = (const float*)d_in[25];
    const float* hW1   = (const float*)d_in[26];
    const float* hb1   = (const float*)d_in[27];
    const float* hW2   = (const float*)d_in[28];
    const float* hb2   = (const float*)d_in[29];
    float* out = (float*)d_out;

    cudaFuncSetAttribute(mma_gemm_k, cudaFuncAttributeMaxDynamicSharedMemorySize, SMEM_GEMM);

    const int nblkN = (NN + 255) / 256;
    const int nblkE = (EE + 255) / 256;
    const int tileG = (NN + 127) / 128;
    const int aggG  = (NN + 7) / 8;

    init_k<<<nblkN, 256>>>();
    edge_mlp_k<<<nblkE, 256>>>(ea, eeW1, eeb1, eeW2, eeb2);
    count_deg_k<<<nblkE, 256>>>(ei + EE);
    dis_k<<<nblkN, 256>>>();
    scan_k<<<1, 1024>>>();
    fill_k<<<nblkE, 256>>>(ei, ei + EE);
    prep_k<<<5, 128>>>(resW, W[0], W[1], W[2], W[3]);

    // residual projection for layer 0: x @ resW + resB -> d_res0
    mma_gemm_k<<<tileG, 256, SMEM_GEMM>>>(x, 0, 1, 0, IN_C, resB);
    // layer 0
    mma_gemm_k<<<tileG, 256, SMEM_GEMM>>>(x, 0, 0, 1, IN_C, nullptr);
    agg_ln_k<<<aggG, 256>>>(cbp[0], gm[0], be[0], 0, 1, 1);
    // layer 1
    mma_gemm_k<<<tileG, 256, SMEM_GEMM>>>(nullptr, 1, 0, 2, HID, nullptr);
    agg_ln_k<<<aggG, 256>>>(cbp[1], gm[1], be[1], 1, 2, 0);
    // layer 2
    mma_gemm_k<<<tileG, 256, SMEM_GEMM>>>(nullptr, 2, 0, 3, HID, nullptr);
    agg_ln_k<<<aggG, 256>>>(cbp[2], gm[2], be[2], 2, 1, 0);
    // layer 3
    mma_gemm_k<<<tileG, 256, SMEM_GEMM>>>(nullptr, 1, 0, 4, HID, nullptr);
    agg_ln_k<<<aggG, 256>>>(cbp[3], gm[3], be[3], 1, 2, 0);

    mark_k<<<nblkN, 256>>>(batch);
    fix_k<<<1, 512>>>();
    pool_k<<<GG, 128>>>();
    head_k<<<GG, 128>>>(hW1, hb1, hW2, hb2, out);
}